// round 16
// baseline (speedup 1.0000x reference)
#include <cuda_runtime.h>
#include <cuda_fp16.h>
#include <math.h>

// WaveNet collapsed to the last-sample 32-dim recurrence (k=0 tap only),
// residual folded into next layer's filter/gate at pack time, log2e baked:
//   A_L = -2*log2e*F_{L+1}(R_L+I), B_L = -log2e*G_{L+1}(R_L+I)
//   e1 = 2^(A u), e2 = 2^(B u);  u = (1-e1)/((1+e1)(1+e2))
//   skip += S_L u;  out = end2 @ relu(end1 @ relu(skip) + b1) + b2
//
// R16 = R15 + half2 skip/head arithmetic:
//   u stored to smem as fp16; skip GEMM = LDG.128(8 fp16 w) + uniform
//   LDS.128(8 fp16 u) + 4 HFMA2, folded to fp32 every 8 k-groups.
//   Same for the end1 head. ~2x fewer issue slots in the skip warps.

#define NL   40
#define RC   32
#define SC   256
#define CIN  6
#define T_IN 8192
#define FULLM 0xffffffffu

#define CH   8                 // layers per chunk
#define NCH  (NL / CH)         // 5
#define LW   512               // float4 per layer (A@0, B@256)
#define CW   (CH * LW)         // float4 per chunk = 4096
#define RING_BYTES (2 * CW * 16)   // 131072

typedef unsigned long long u64;

__device__ float  g_pk[NL * 2048];           // folded A/B, fp32, 328 KB
__device__ __half g_skipH[(NL * RC) * SC];   // [kg8][c][8kk] fp16, 655 KB
__device__ __half g_end1H[SC * SC];          // [jg8][c][8jj] fp16, 128 KB
__device__ float  g_xs0[8 * RC];

__device__ __forceinline__ void fma2(u64& d, u64 a, u64 b) {
    asm("fma.rn.f32x2 %0, %1, %2, %3;" : "=l"(d) : "l"(a), "l"(b), "l"(d));
}
__device__ __forceinline__ void add2(u64& d, u64 a, u64 b) {
    asm("add.rn.f32x2 %0, %1, %2;" : "=l"(d) : "l"(a), "l"(b));
}
__device__ __forceinline__ float2 upk(u64 v) {
    float2 r; asm("mov.b64 {%0, %1}, %2;" : "=f"(r.x), "=f"(r.y) : "l"(v));
    return r;
}
__device__ __forceinline__ float ex2(float v) {
    float r; asm("ex2.approx.f32 %0, %1;" : "=f"(r) : "f"(v));
    return r;
}
__device__ __forceinline__ unsigned h2u(__half2 h) {
    unsigned u; *reinterpret_cast<__half2*>(&u) = h; return u;
}
__device__ __forceinline__ __half2 u2h(unsigned u) {
    return *reinterpret_cast<__half2*>(&u);
}
__device__ __forceinline__ uint4 pack8h(float4 a, float4 c) {
    uint4 o;
    o.x = h2u(__floats2half2_rn(a.x, a.y));
    o.y = h2u(__floats2half2_rn(a.z, a.w));
    o.z = h2u(__floats2half2_rn(c.x, c.y));
    o.w = h2u(__floats2half2_rn(c.z, c.w));
    return o;
}

// ---------------------------------------------------------------- pack
// blocks 0..39: fold matmul; blocks 40+: fp16 skipT/end1T copies + start.
__global__ __launch_bounds__(256, 1)
void wn_pack(const float* __restrict__ x,
             const float* __restrict__ start_w,
             const float* __restrict__ filter_w,
             const float* __restrict__ gate_w,
             const float* __restrict__ res_w,
             const float* __restrict__ skip_w,
             const float* __restrict__ end1_w)
{
    const int blk = blockIdx.x;
    const int tid = threadIdx.x;

    if (blk < NL) {
        // ---- per-layer fold: slot L uses F/G of layer L, R of layer L-1
        const int L = blk;
        const float LOG2E = 1.4426950408889634f;
        __shared__ float Fk[RC][RC];   // -2*log2e * filter k0 taps
        __shared__ float Gk[RC][RC];   // -log2e   * gate   k0 taps
        __shared__ float Rp[RC][RC];   // R_{L-1} + I

        #pragma unroll
        for (int s = 0; s < 2; s++) {
            const int d  = tid + 256 * s;
            const int i  = d >> 4;
            const int rm = d & 15;
            const float4 fv = *(const float4*)(filter_w + L * 2048 + 4 * d);
            const float4 gv = *(const float4*)(gate_w   + L * 2048 + 4 * d);
            Fk[i][2 * rm]     = -2.f * LOG2E * fv.x;
            Fk[i][2 * rm + 1] = -2.f * LOG2E * fv.z;
            Gk[i][2 * rm]     = -LOG2E * gv.x;
            Gk[i][2 * rm + 1] = -LOG2E * gv.z;
        }
        if (L > 0) {
            const int k  = tid >> 3;
            const int j0 = (tid & 7) * 4;
            float4 r4 = *(const float4*)(res_w + (L - 1) * 1024 + k * RC + j0);
            if (k >= j0 && k < j0 + 4) (&r4.x)[k - j0] += 1.f;
            *(float4*)&Rp[k][j0] = r4;
        }
        __syncthreads();

        const int jg = tid >> 5;
        const int i  = tid & 31;
        float4 accA, accB;
        if (L == 0) {
            accA = *(const float4*)&Fk[i][4 * jg];
            accB = *(const float4*)&Gk[i][4 * jg];
        } else {
            accA = make_float4(0.f, 0.f, 0.f, 0.f);
            accB = make_float4(0.f, 0.f, 0.f, 0.f);
            #pragma unroll
            for (int k = 0; k < RC; k++) {
                const float4 r4 = *(const float4*)&Rp[k][4 * jg];
                const float fv = Fk[i][k];
                const float gv = Gk[i][k];
                accA.x = fmaf(fv, r4.x, accA.x); accA.y = fmaf(fv, r4.y, accA.y);
                accA.z = fmaf(fv, r4.z, accA.z); accA.w = fmaf(fv, r4.w, accA.w);
                accB.x = fmaf(gv, r4.x, accB.x); accB.y = fmaf(gv, r4.y, accB.y);
                accB.z = fmaf(gv, r4.z, accB.z); accB.w = fmaf(gv, r4.w, accB.w);
            }
        }
        ((float4*)g_pk)[L * LW + jg * 32 + i]       = accA;
        ((float4*)g_pk)[L * LW + 256 + jg * 32 + i] = accB;
    } else {
        // ---- copies: skipH (40960 u4), end1H (8192 u4), xs0 (256)
        const int NB = NL * RC * SC / 8;   // 40960
        const int NC = SC * SC / 8;        // 8192
        const int total = NB + NC + 8 * RC;
        const int nthr = 128 * 256;
        for (int idx = (blk - NL) * 256 + tid; idx < total; idx += nthr) {
            if (idx < NB) {
                const int kg8 = idx >> 8;
                const int c   = idx & 255;
                const int k0  = kg8 * 8;
                const int L   = k0 >> 5;
                const int j0  = k0 & 31;
                const float* src = skip_w + L * (SC * RC) + c * RC + j0;
                ((uint4*)g_skipH)[idx] =
                    pack8h(*(const float4*)src, *(const float4*)(src + 4));
            } else if (idx < NB + NC) {
                const int t   = idx - NB;
                const int jg8 = t >> 8;
                const int c   = t & 255;
                const float* src = end1_w + c * SC + jg8 * 8;
                ((uint4*)g_end1H)[t] =
                    pack8h(*(const float4*)src, *(const float4*)(src + 4));
            } else {
                const int t = idx - NB - NC;
                const int b = t / RC, i = t % RC;
                float s = 0.f;
                #pragma unroll
                for (int ci = 0; ci < CIN; ci++)
                    s += start_w[i * CIN + ci] * x[(b * CIN + ci) * T_IN + (T_IN - 1)];
                g_xs0[b * RC + i] = s;
            }
        }
    }
}

// ---------------------------------------------------------------- main
extern __shared__ float ring[];    // RING_BYTES dynamic smem

__global__ __launch_bounds__(288, 1)
void wn_main(const float* __restrict__ end1_b,
             const float* __restrict__ end2_w,
             const float* __restrict__ end2_b,
             float* __restrict__ out)
{
    const int b    = blockIdx.x;
    const int tid  = threadIdx.x;
    const int lane = tid & 31;
    const int warp = tid >> 5;

    __shared__ __align__(16) __half us_h[NL * RC];    // u as fp16, 2.5 KB
    __shared__ __align__(16) float vbuf[2][RC];       // ping-pong state
    __shared__ __align__(16) __half hs_h[SC];         // relu(skip) as fp16
    __shared__ float red8[8];

    // skip-thread channel: warps 1-8 -> c0 = tid-32 in [0,256), 1/thread.
    const int c0 = tid - 32;
    float acc0 = 0.f;

    // prologue: copy chunk 0 (256 threads x 16 float4, exact)
    if (tid < 256) {
        const float4* src = (const float4*)g_pk;
        float4*       dst = (float4*)ring;
        float4 t[16];
        #pragma unroll
        for (int k = 0; k < 16; k++) t[k] = src[tid + 256 * k];
        #pragma unroll
        for (int k = 0; k < 16; k++) dst[tid + 256 * k] = t[k];
    }
    if (warp == 0) vbuf[0][lane] = g_xs0[b * RC + lane];
    __syncthreads();

    for (int q = 0; q <= NCH; q++) {
        if (warp == 0) {
            if (q < NCH) {
                const float4* wc = (const float4*)ring + (q & 1) * CW;
                #pragma unroll
                for (int l = 0; l < CH; l++) {
                    const int L   = q * CH + l;
                    const int par = l & 1;          // CH even => par == L&1
                    const float4* wl = wc + l * LW + lane;

                    u64 fa = 0ull, fb = 0ull, ga = 0ull, gb = 0ull;
                    #pragma unroll
                    for (int jg = 0; jg < 8; jg++) {
                        const ulonglong2 vv = *(const ulonglong2*)&vbuf[par][4 * jg];
                        const ulonglong2 Aw = *(const ulonglong2*)(wl + jg * 32);
                        const ulonglong2 Bw = *(const ulonglong2*)(wl + 256 + jg * 32);
                        fma2(fa, Aw.x, vv.x); fma2(fb, Aw.y, vv.y);
                        fma2(ga, Bw.x, vv.x); fma2(gb, Bw.y, vv.y);
                    }
                    add2(fa, fa, fb);
                    add2(ga, ga, gb);
                    const float2 fp = upk(fa);
                    const float2 gp = upk(ga);
                    const float e1 = ex2(fp.x + fp.y);   // e^{-2f}
                    const float e2 = ex2(gp.x + gp.y);   // e^{-g}
                    // u = tanh(f)*sig(g) = (1-e1)/((1+e1)(1+e2))
                    const float u = __fdividef(1.f - e1, (1.f + e1) * (1.f + e2));
                    us_h[L * RC + lane] = __float2half(u);
                    vbuf[par ^ 1][lane] = u;
                    __syncwarp();
                }
            }
        } else {
            // producers: batched stage of chunk q+1 (256 threads x 16 f4)
            if (q + 1 < NCH) {
                const float4* src = (const float4*)g_pk + (q + 1) * CW;
                float4*       dst = (float4*)ring + ((q + 1) & 1) * CW;
                float4 t[16];
                #pragma unroll
                for (int k = 0; k < 16; k++) t[k] = src[c0 + 256 * k];
                #pragma unroll
                for (int k = 0; k < 16; k++) dst[c0 + 256 * k] = t[k];
            }
            // half2 skip GEMM for chunk q-1: 32 k-groups of 8
            if (q >= 1) {
                const int cq = q - 1;
                const uint4* sp  = (const uint4*)g_skipH + (32 * cq) * 256 + c0;
                const uint4* uhp = (const uint4*)us_h + cq * 32;
                __half2 a0 = u2h(0u), a1 = u2h(0u), a2 = u2h(0u), a3 = u2h(0u);
                #pragma unroll
                for (int kg8 = 0; kg8 < 32; kg8++) {
                    const uint4 s8 = sp[kg8 * 256];
                    const uint4 u8 = uhp[kg8];
                    a0 = __hfma2(u2h(s8.x), u2h(u8.x), a0);
                    a1 = __hfma2(u2h(s8.y), u2h(u8.y), a1);
                    a2 = __hfma2(u2h(s8.z), u2h(u8.z), a2);
                    a3 = __hfma2(u2h(s8.w), u2h(u8.w), a3);
                    if ((kg8 & 7) == 7) {
                        const float2 f0 = __half22float2(a0);
                        const float2 f1 = __half22float2(a1);
                        const float2 f2 = __half22float2(a2);
                        const float2 f3 = __half22float2(a3);
                        acc0 += ((f0.x + f0.y) + (f1.x + f1.y))
                              + ((f2.x + f2.y) + (f3.x + f3.y));
                        a0 = u2h(0u); a1 = u2h(0u); a2 = u2h(0u); a3 = u2h(0u);
                    }
                }
            }
        }
        __syncthreads();
    }

    // ---- head (half2 end1), one channel per skip thread
    if (warp > 0) hs_h[c0] = __float2half(fmaxf(acc0, 0.f));
    __syncthreads();

    float o = 0.f;
    if (warp > 0) {
        float e0 = end1_b[c0];
        const uint4* ep  = (const uint4*)g_end1H + c0;
        const uint4* hhp = (const uint4*)hs_h;
        __half2 a0 = u2h(0u), a1 = u2h(0u), a2 = u2h(0u), a3 = u2h(0u);
        #pragma unroll
        for (int jg8 = 0; jg8 < 32; jg8++) {
            const uint4 s8 = ep[jg8 * 256];
            const uint4 h8 = hhp[jg8];
            a0 = __hfma2(u2h(s8.x), u2h(h8.x), a0);
            a1 = __hfma2(u2h(s8.y), u2h(h8.y), a1);
            a2 = __hfma2(u2h(s8.z), u2h(h8.z), a2);
            a3 = __hfma2(u2h(s8.w), u2h(h8.w), a3);
            if ((jg8 & 7) == 7) {
                const float2 f0 = __half22float2(a0);
                const float2 f1 = __half22float2(a1);
                const float2 f2 = __half22float2(a2);
                const float2 f3 = __half22float2(a3);
                e0 += ((f0.x + f0.y) + (f1.x + f1.y))
                    + ((f2.x + f2.y) + (f3.x + f3.y));
                a0 = u2h(0u); a1 = u2h(0u); a2 = u2h(0u); a3 = u2h(0u);
            }
        }
        o = end2_w[c0] * fmaxf(e0, 0.f);
    }
    #pragma unroll
    for (int off = 16; off > 0; off >>= 1)
        o += __shfl_xor_sync(FULLM, o, off);
    if (warp > 0 && lane == 0) red8[warp - 1] = o;
    __syncthreads();
    if (tid == 0) {
        float tot = 0.f;
        #pragma unroll
        for (int w = 0; w < 8; w++) tot += red8[w];
        out[b] = tot + end2_b[0];
    }
}

extern "C" void kernel_launch(void* const* d_in, const int* in_sizes, int n_in,
                              void* d_out, int out_size)
{
    const float* x        = (const float*)d_in[0];
    const float* start_w  = (const float*)d_in[1];
    const float* filter_w = (const float*)d_in[2];
    const float* gate_w   = (const float*)d_in[3];
    const float* res_w    = (const float*)d_in[4];
    const float* skip_w   = (const float*)d_in[5];
    const float* end1_w   = (const float*)d_in[6];
    const float* end1_b   = (const float*)d_in[7];
    const float* end2_w   = (const float*)d_in[8];
    const float* end2_b   = (const float*)d_in[9];
    float* out = (float*)d_out;

    cudaFuncSetAttribute(wn_main,
                         cudaFuncAttributeMaxDynamicSharedMemorySize,
                         RING_BYTES);

    wn_pack<<<168, 256>>>(x, start_w, filter_w, gate_w, res_w, skip_w, end1_w);
    wn_main<<<8, 288, RING_BYTES>>>(end1_b, end2_w, end2_b, out);
}

// round 17
// speedup vs baseline: 1.0204x; 1.0204x over previous
#include <cuda_runtime.h>
#include <cuda_fp16.h>
#include <math.h>

// WaveNet collapsed to the last-sample 32-dim recurrence (k=0 tap only),
// residual folded into next layer's filter/gate, log2e baked:
//   A_L = -2*log2e*F_{L+1}(R_L+I), B_L = -log2e*G_{L+1}(R_L+I)
//   e1 = 2^(A u), e2 = 2^(B u);  u = (1-e1)/((1+e1)(1+e2))
//   skip += S_L u;  out = end2 @ relu(end1 @ relu(skip) + b1) + b2
//
// R17 = R15 main (fp32-accum fp16 skip/end1) merged into ONE kernel:
//   grid 168 x 288.  blocks 0-7: main (batch b), spin-wait on pack-done.
//   blocks 8-47: per-layer fold matmul.  blocks 48-167: fp16 copies + start.
//   Monotone counters (g_tick/g_done) make the spin graph-replay-safe.

#define NL   40
#define RC   32
#define SC   256
#define CIN  6
#define T_IN 8192
#define FULLM 0xffffffffu

#define CH   8                 // layers per chunk
#define NCH  (NL / CH)         // 5
#define LW   512               // float4 per layer (A@0, B@256)
#define CW   (CH * LW)         // float4 per chunk = 4096
#define RING_BYTES (2 * CW * 16)   // 131072

#define GRID      168
#define NPACK     160          // packer blocks (fold 40 + copy 120)

typedef unsigned long long u64;

__device__ float    g_pk[NL * 2048];           // folded A/B, fp32, 328 KB
__device__ __half   g_skipH[(NL * RC) * SC];   // [kg8][c][8kk] fp16, 655 KB
__device__ __half   g_end1H[SC * SC];          // [jg8][c][8jj] fp16, 128 KB
__device__ float    g_xs0[8 * RC];
__device__ unsigned g_tick;                    // zero-init, monotone
__device__ unsigned g_done;                    // zero-init, monotone

__device__ __forceinline__ void fma2(u64& d, u64 a, u64 b) {
    asm("fma.rn.f32x2 %0, %1, %2, %3;" : "=l"(d) : "l"(a), "l"(b), "l"(d));
}
__device__ __forceinline__ void add2(u64& d, u64 a, u64 b) {
    asm("add.rn.f32x2 %0, %1, %2;" : "=l"(d) : "l"(a), "l"(b));
}
__device__ __forceinline__ float2 upk(u64 v) {
    float2 r; asm("mov.b64 {%0, %1}, %2;" : "=f"(r.x), "=f"(r.y) : "l"(v));
    return r;
}
__device__ __forceinline__ float ex2(float v) {
    float r; asm("ex2.approx.f32 %0, %1;" : "=f"(r) : "f"(v));
    return r;
}
__device__ __forceinline__ unsigned h2u(__half2 h) {
    unsigned u; *reinterpret_cast<__half2*>(&u) = h; return u;
}
__device__ __forceinline__ __half2 u2h(unsigned u) {
    return *reinterpret_cast<__half2*>(&u);
}
__device__ __forceinline__ uint4 pack8h(float4 a, float4 c) {
    uint4 o;
    o.x = h2u(__floats2half2_rn(a.x, a.y));
    o.y = h2u(__floats2half2_rn(a.z, a.w));
    o.z = h2u(__floats2half2_rn(c.x, c.y));
    o.w = h2u(__floats2half2_rn(c.z, c.w));
    return o;
}
__device__ __forceinline__ float dot8h(uint4 s8, const float* u) {
    const float2 p0 = __half22float2(u2h(s8.x));
    const float2 p1 = __half22float2(u2h(s8.y));
    const float2 p2 = __half22float2(u2h(s8.z));
    const float2 p3 = __half22float2(u2h(s8.w));
    float a = fmaf(p0.x, u[0], 0.f);
    a = fmaf(p0.y, u[1], a);
    a = fmaf(p1.x, u[2], a);
    a = fmaf(p1.y, u[3], a);
    a = fmaf(p2.x, u[4], a);
    a = fmaf(p2.y, u[5], a);
    a = fmaf(p3.x, u[6], a);
    a = fmaf(p3.y, u[7], a);
    return a;
}

extern __shared__ float ring[];    // RING_BYTES dynamic smem (main blocks)

__global__ __launch_bounds__(288, 1)
void wn_all(const float* __restrict__ x,
            const float* __restrict__ start_w,
            const float* __restrict__ filter_w,
            const float* __restrict__ gate_w,
            const float* __restrict__ res_w,
            const float* __restrict__ skip_w,
            const float* __restrict__ end1_w,
            const float* __restrict__ end1_b,
            const float* __restrict__ end2_w,
            const float* __restrict__ end2_b,
            float* __restrict__ out)
{
    const int blk  = blockIdx.x;
    const int tid  = threadIdx.x;
    const int lane = tid & 31;
    const int warp = tid >> 5;

    if (blk >= 8 && blk < 8 + NL) {
        // ================= fold block: layer slot L =================
        const int L = blk - 8;
        const float LOG2E = 1.4426950408889634f;
        __shared__ float Fk[RC][RC];   // -2*log2e * filter k0 taps
        __shared__ float Gk[RC][RC];   // -log2e   * gate   k0 taps
        __shared__ float Rp[RC][RC];   // R_{L-1} + I

        if (tid < 256) {
            #pragma unroll
            for (int s = 0; s < 2; s++) {
                const int d  = tid + 256 * s;
                const int i  = d >> 4;
                const int rm = d & 15;
                const float4 fv = *(const float4*)(filter_w + L * 2048 + 4 * d);
                const float4 gv = *(const float4*)(gate_w   + L * 2048 + 4 * d);
                Fk[i][2 * rm]     = -2.f * LOG2E * fv.x;
                Fk[i][2 * rm + 1] = -2.f * LOG2E * fv.z;
                Gk[i][2 * rm]     = -LOG2E * gv.x;
                Gk[i][2 * rm + 1] = -LOG2E * gv.z;
            }
            if (L > 0) {
                const int k  = tid >> 3;
                const int j0 = (tid & 7) * 4;
                float4 r4 = *(const float4*)(res_w + (L - 1) * 1024 + k * RC + j0);
                if (k >= j0 && k < j0 + 4) (&r4.x)[k - j0] += 1.f;
                *(float4*)&Rp[k][j0] = r4;
            }
        }
        __syncthreads();

        if (tid < 256) {
            const int jg = tid >> 5;
            const int i  = tid & 31;
            float4 accA, accB;
            if (L == 0) {
                accA = *(const float4*)&Fk[i][4 * jg];
                accB = *(const float4*)&Gk[i][4 * jg];
            } else {
                accA = make_float4(0.f, 0.f, 0.f, 0.f);
                accB = make_float4(0.f, 0.f, 0.f, 0.f);
                #pragma unroll
                for (int k = 0; k < RC; k++) {
                    const float4 r4 = *(const float4*)&Rp[k][4 * jg];
                    const float fv = Fk[i][k];
                    const float gv = Gk[i][k];
                    accA.x = fmaf(fv, r4.x, accA.x); accA.y = fmaf(fv, r4.y, accA.y);
                    accA.z = fmaf(fv, r4.z, accA.z); accA.w = fmaf(fv, r4.w, accA.w);
                    accB.x = fmaf(gv, r4.x, accB.x); accB.y = fmaf(gv, r4.y, accB.y);
                    accB.z = fmaf(gv, r4.z, accB.z); accB.w = fmaf(gv, r4.w, accB.w);
                }
            }
            ((float4*)g_pk)[L * LW + jg * 32 + i]       = accA;
            ((float4*)g_pk)[L * LW + 256 + jg * 32 + i] = accB;
        }
        __threadfence();
        __syncthreads();
        if (tid == 0) atomicAdd(&g_done, 1u);
        return;
    }

    if (blk >= 8 + NL) {
        // ================= copy block =================
        const int NB = NL * RC * SC / 8;   // 40960 uint4
        const int NC = SC * SC / 8;        // 8192 uint4
        const int total = NB + NC + 8 * RC;
        const int nthr = (GRID - 8 - NL) * 288;     // 120*288
        for (int idx = (blk - 8 - NL) * 288 + tid; idx < total; idx += nthr) {
            if (idx < NB) {
                const int kg8 = idx >> 8;
                const int c   = idx & 255;
                const int k0  = kg8 * 8;
                const int L   = k0 >> 5;
                const int j0  = k0 & 31;
                const float* src = skip_w + L * (SC * RC) + c * RC + j0;
                ((uint4*)g_skipH)[idx] =
                    pack8h(*(const float4*)src, *(const float4*)(src + 4));
            } else if (idx < NB + NC) {
                const int t   = idx - NB;
                const int jg8 = t >> 8;
                const int c   = t & 255;
                const float* src = end1_w + c * SC + jg8 * 8;
                ((uint4*)g_end1H)[t] =
                    pack8h(*(const float4*)src, *(const float4*)(src + 4));
            } else {
                const int t = idx - NB - NC;
                const int b = t / RC, i = t % RC;
                float s = 0.f;
                #pragma unroll
                for (int ci = 0; ci < CIN; ci++)
                    s += start_w[i * CIN + ci] * x[(b * CIN + ci) * T_IN + (T_IN - 1)];
                g_xs0[b * RC + i] = s;
            }
        }
        __threadfence();
        __syncthreads();
        if (tid == 0) atomicAdd(&g_done, 1u);
        return;
    }

    // ================= main block (batch b = blk) =================
    const int b = blk;

    __shared__ __align__(16) float us_all[NL * RC];   // 5.1 KB
    __shared__ __align__(16) float vbuf[2][RC];       // ping-pong state
    __shared__ __align__(16) float hs[SC];
    __shared__ float red8[8];

    // wait for all packers (monotone counters => graph-replay safe)
    if (tid == 0) {
        const unsigned li  = atomicAdd(&g_tick, 1u) / 8u;
        const unsigned tgt = (li + 1u) * NPACK;
        while (*(volatile unsigned*)&g_done < tgt) { }
    }
    __syncthreads();
    __threadfence();

    // skip-thread channel: warps 1-8 -> c0 = tid-32 in [0,256), 1/thread.
    const int c0 = tid - 32;
    float acc0 = 0.f;

    // prologue: copy chunk 0 (256 threads x 16 float4, exact)
    if (tid < 256) {
        const float4* src = (const float4*)g_pk;
        float4*       dst = (float4*)ring;
        float4 t[16];
        #pragma unroll
        for (int k = 0; k < 16; k++) t[k] = src[tid + 256 * k];
        #pragma unroll
        for (int k = 0; k < 16; k++) dst[tid + 256 * k] = t[k];
    }
    if (warp == 0) vbuf[0][lane] = g_xs0[b * RC + lane];
    __syncthreads();

    for (int q = 0; q <= NCH; q++) {
        if (warp == 0) {
            if (q < NCH) {
                const float4* wc = (const float4*)ring + (q & 1) * CW;
                #pragma unroll
                for (int l = 0; l < CH; l++) {
                    const int L   = q * CH + l;
                    const int par = l & 1;          // CH even => par == L&1
                    const float4* wl = wc + l * LW + lane;

                    u64 fa = 0ull, fb = 0ull, ga = 0ull, gb = 0ull;
                    #pragma unroll
                    for (int jg = 0; jg < 8; jg++) {
                        const ulonglong2 vv = *(const ulonglong2*)&vbuf[par][4 * jg];
                        const ulonglong2 Aw = *(const ulonglong2*)(wl + jg * 32);
                        const ulonglong2 Bw = *(const ulonglong2*)(wl + 256 + jg * 32);
                        fma2(fa, Aw.x, vv.x); fma2(fb, Aw.y, vv.y);
                        fma2(ga, Bw.x, vv.x); fma2(gb, Bw.y, vv.y);
                    }
                    add2(fa, fa, fb);
                    add2(ga, ga, gb);
                    const float2 fp = upk(fa);
                    const float2 gp = upk(ga);
                    const float e1 = ex2(fp.x + fp.y);   // e^{-2f}
                    const float e2 = ex2(gp.x + gp.y);   // e^{-g}
                    // u = tanh(f)*sig(g) = (1-e1)/((1+e1)(1+e2))
                    const float u = __fdividef(1.f - e1, (1.f + e1) * (1.f + e2));
                    us_all[L * RC + lane] = u;
                    vbuf[par ^ 1][lane] = u;
                    __syncwarp();
                }
            }
        } else {
            // producers: batched stage of chunk q+1 (256 threads x 16 f4)
            if (q + 1 < NCH) {
                const float4* src = (const float4*)g_pk + (q + 1) * CW;
                float4*       dst = (float4*)ring + ((q + 1) & 1) * CW;
                float4 t[16];
                #pragma unroll
                for (int k = 0; k < 16; k++) t[k] = src[c0 + 256 * k];
                #pragma unroll
                for (int k = 0; k < 16; k++) dst[c0 + 256 * k] = t[k];
            }
            // fp16 skip GEMM for chunk q-1: 32 k-groups of 8, one channel
            if (q >= 1) {
                const int cq = q - 1;
                const uint4* sp = (const uint4*)g_skipH + (32 * cq) * 256 + c0;
                const float* up = us_all + cq * (CH * RC);
                #pragma unroll
                for (int kg8 = 0; kg8 < 32; kg8++)
                    acc0 += dot8h(sp[kg8 * 256], up + 8 * kg8);
            }
        }
        __syncthreads();
    }

    // ---- head (fp16 end1), one channel per skip thread
    if (warp > 0) hs[c0] = fmaxf(acc0, 0.f);
    __syncthreads();

    float o = 0.f;
    if (warp > 0) {
        float e0 = end1_b[c0];
        const uint4* ep = (const uint4*)g_end1H + c0;
        #pragma unroll
        for (int jg8 = 0; jg8 < 32; jg8++)
            e0 += dot8h(ep[jg8 * 256], hs + 8 * jg8);
        o = end2_w[c0] * fmaxf(e0, 0.f);
    }
    #pragma unroll
    for (int off = 16; off > 0; off >>= 1)
        o += __shfl_xor_sync(FULLM, o, off);
    if (warp > 0 && lane == 0) red8[warp - 1] = o;
    __syncthreads();
    if (tid == 0) {
        float tot = 0.f;
        #pragma unroll
        for (int w = 0; w < 8; w++) tot += red8[w];
        out[b] = tot + end2_b[0];
    }
}

extern "C" void kernel_launch(void* const* d_in, const int* in_sizes, int n_in,
                              void* d_out, int out_size)
{
    const float* x        = (const float*)d_in[0];
    const float* start_w  = (const float*)d_in[1];
    const float* filter_w = (const float*)d_in[2];
    const float* gate_w   = (const float*)d_in[3];
    const float* res_w    = (const float*)d_in[4];
    const float* skip_w   = (const float*)d_in[5];
    const float* end1_w   = (const float*)d_in[6];
    const float* end1_b   = (const float*)d_in[7];
    const float* end2_w   = (const float*)d_in[8];
    const float* end2_b   = (const float*)d_in[9];
    float* out = (float*)d_out;

    cudaFuncSetAttribute(wn_all,
                         cudaFuncAttributeMaxDynamicSharedMemorySize,
                         RING_BYTES);

    wn_all<<<GRID, 288, RING_BYTES>>>(x, start_w, filter_w, gate_w, res_w,
                                      skip_w, end1_w, end1_b, end2_w, end2_b,
                                      out);
}